// round 1
// baseline (speedup 1.0000x reference)
#include <cuda_runtime.h>

// SpatialTransformer: trilinear grid-sample with border padding, align_corners=True.
// src  [B=2, C=1, D=160, H=192, W=224] fp32
// flow [B=2, 3,        D,      H,     W] fp32  (components: d, h, w displacement)
// out  [B=2, C=1, D, H, W] fp32
//
// out[b,0,d,h,w] = trilinear(src[b,0], clamp(d+flow0), clamp(h+flow1), clamp(w+flow2))

#define DD 160
#define HH 192
#define WW 224
#define BB 2
#define HW (HH * WW)
#define DHW (DD * HH * WW)

__device__ __forceinline__ float sample_one(const float* __restrict__ sv,
                                            float cd, float ch, float cw) {
    // clamp to border
    cd = fminf(fmaxf(cd, 0.0f), (float)(DD - 1));
    ch = fminf(fmaxf(ch, 0.0f), (float)(HH - 1));
    cw = fminf(fmaxf(cw, 0.0f), (float)(WW - 1));

    int d0 = (int)floorf(cd);
    int h0 = (int)floorf(ch);
    int w0 = (int)floorf(cw);
    int d1 = min(d0 + 1, DD - 1);
    int h1 = min(h0 + 1, HH - 1);
    int w1 = min(w0 + 1, WW - 1);

    float fd = cd - (float)d0;
    float fh = ch - (float)h0;
    float fw = cw - (float)w0;

    // 4 row bases, 8 gathers
    int b00 = d0 * HW + h0 * WW;
    int b01 = d0 * HW + h1 * WW;
    int b10 = d1 * HW + h0 * WW;
    int b11 = d1 * HW + h1 * WW;

    float c000 = __ldg(sv + b00 + w0);
    float c001 = __ldg(sv + b00 + w1);
    float c010 = __ldg(sv + b01 + w0);
    float c011 = __ldg(sv + b01 + w1);
    float c100 = __ldg(sv + b10 + w0);
    float c101 = __ldg(sv + b10 + w1);
    float c110 = __ldg(sv + b11 + w0);
    float c111 = __ldg(sv + b11 + w1);

    // lerp along w, then h, then d (7 lerps, FMA-friendly)
    float c00 = fmaf(fw, c001 - c000, c000);
    float c01 = fmaf(fw, c011 - c010, c010);
    float c10 = fmaf(fw, c101 - c100, c100);
    float c11 = fmaf(fw, c111 - c110, c110);
    float c0  = fmaf(fh, c01 - c00, c00);
    float c1  = fmaf(fh, c11 - c10, c10);
    return fmaf(fd, c1 - c0, c0);
}

__global__ __launch_bounds__(256) void spatial_transformer_kernel(
    const float* __restrict__ src,
    const float* __restrict__ flow,
    float* __restrict__ out) {
    int tid = blockIdx.x * blockDim.x + threadIdx.x;
    const int nvec = (BB * DHW) / 4;
    if (tid >= nvec) return;

    int idx = tid * 4;                 // linear output index (first of 4 voxels)
    int b = idx / DHW;
    int s = idx - b * DHW;             // spatial index within batch
    int w = s % WW;
    int t = s / WW;
    int h = t % HH;
    int d = t / HH;

    const float* fl = flow + (size_t)b * 3 * DHW;
    float4 fd4 = *reinterpret_cast<const float4*>(fl + s);
    float4 fh4 = *reinterpret_cast<const float4*>(fl + DHW + s);
    float4 fw4 = *reinterpret_cast<const float4*>(fl + 2 * DHW + s);

    const float* sv = src + (size_t)b * DHW;

    float cd_base = (float)d;
    float ch_base = (float)h;
    float cw_base = (float)w;

    float4 res;
    res.x = sample_one(sv, cd_base + fd4.x, ch_base + fh4.x, cw_base + 0.0f + fw4.x);
    res.y = sample_one(sv, cd_base + fd4.y, ch_base + fh4.y, cw_base + 1.0f + fw4.y);
    res.z = sample_one(sv, cd_base + fd4.z, ch_base + fh4.z, cw_base + 2.0f + fw4.z);
    res.w = sample_one(sv, cd_base + fd4.w, ch_base + fh4.w, cw_base + 3.0f + fw4.w);

    *reinterpret_cast<float4*>(out + idx) = res;
}

extern "C" void kernel_launch(void* const* d_in, const int* in_sizes, int n_in,
                              void* d_out, int out_size) {
    const float* src  = (const float*)d_in[0];
    const float* flow = (const float*)d_in[1];
    float* out = (float*)d_out;

    const int nvec = (BB * DHW) / 4;   // 3,440,640 threads
    const int threads = 256;
    const int blocks = (nvec + threads - 1) / threads;
    spatial_transformer_kernel<<<blocks, threads>>>(src, flow, out);
}

// round 2
// speedup vs baseline: 1.0704x; 1.0704x over previous
#include <cuda_runtime.h>

// SpatialTransformer: trilinear grid-sample, border padding, align_corners=True.
// src  [B=2, C=1, D=160, H=192, W=224] fp32
// flow [B=2, 3, D, H, W] fp32  (components: d, h, w displacement)
// out  [B=2, C=1, D, H, W] fp32
//
// R2: L1-wavefront reduction. Each (w0, w0+1) pair is fetched with ONE
// aligned float4 gather (both elements present when (w0&3)!=3; 25% of lanes
// take a predicated scalar fixup for w1). 8 scalar gathers/voxel -> 4 vector
// gathers + ~1 amortized fixup, ~1.6x fewer L1 wavefronts.

#define DD 160
#define HH 192
#define WW 224
#define BB 2
#define HW (HH * WW)
#define DHW (DD * HH * WW)

__device__ __forceinline__ float sample_one(const float* __restrict__ sv,
                                            float cd, float ch, float cw) {
    // clamp to border
    cd = fminf(fmaxf(cd, 0.0f), (float)(DD - 1));
    ch = fminf(fmaxf(ch, 0.0f), (float)(HH - 1));
    cw = fminf(fmaxf(cw, 0.0f), (float)(WW - 1));

    // coords are >= 0 so truncation == floor
    int d0 = (int)cd;
    int h0 = (int)ch;
    int w0 = (int)cw;
    int d1 = min(d0 + 1, DD - 1);
    int h1 = min(h0 + 1, HH - 1);
    int w1 = min(w0 + 1, WW - 1);

    float fd = cd - (float)d0;
    float fh = ch - (float)h0;
    float fw = cw - (float)w0;

    int b00 = d0 * HW + h0 * WW;
    int b01 = d0 * HW + h1 * WW;
    int b10 = d1 * HW + h0 * WW;
    int b11 = d1 * HW + h1 * WW;

    int a = w0 & ~3;        // 16B-aligned element offset within the row
    int r = w0 & 3;
    bool p0 = (r == 0), p1 = (r == 1), p2 = (r == 2);
    bool cross = (r == 3);

    // 4 vector gathers (each covers w0 and, unless crossing, w0+1)
    float4 v00 = __ldg(reinterpret_cast<const float4*>(sv + b00 + a));
    float4 v01 = __ldg(reinterpret_cast<const float4*>(sv + b01 + a));
    float4 v10 = __ldg(reinterpret_cast<const float4*>(sv + b10 + a));
    float4 v11 = __ldg(reinterpret_cast<const float4*>(sv + b11 + a));

    float c000 = p0 ? v00.x : p1 ? v00.y : p2 ? v00.z : v00.w;
    float c010 = p0 ? v01.x : p1 ? v01.y : p2 ? v01.z : v01.w;
    float c100 = p0 ? v10.x : p1 ? v10.y : p2 ? v10.z : v10.w;
    float c110 = p0 ? v11.x : p1 ? v11.y : p2 ? v11.z : v11.w;

    float c001 = p0 ? v00.y : p1 ? v00.z : v00.w;
    float c011 = p0 ? v01.y : p1 ? v01.z : v01.w;
    float c101 = p0 ? v10.y : p1 ? v10.z : v10.w;
    float c111 = p0 ? v11.y : p1 ? v11.z : v11.w;

    if (cross) {   // ~25% of lanes: w1 lives in the next aligned float4
        c001 = __ldg(sv + b00 + w1);
        c011 = __ldg(sv + b01 + w1);
        c101 = __ldg(sv + b10 + w1);
        c111 = __ldg(sv + b11 + w1);
    }

    // lerp w, then h, then d
    float c00 = fmaf(fw, c001 - c000, c000);
    float c01 = fmaf(fw, c011 - c010, c010);
    float c10 = fmaf(fw, c101 - c100, c100);
    float c11 = fmaf(fw, c111 - c110, c110);
    float c0  = fmaf(fh, c01 - c00, c00);
    float c1  = fmaf(fh, c11 - c10, c10);
    return fmaf(fd, c1 - c0, c0);
}

__global__ __launch_bounds__(256) void spatial_transformer_kernel(
    const float* __restrict__ src,
    const float* __restrict__ flow,
    float* __restrict__ out) {
    int tid = blockIdx.x * blockDim.x + threadIdx.x;
    const int nvec = (BB * DHW) / 4;
    if (tid >= nvec) return;

    int idx = tid * 4;                 // first of 4 consecutive-W voxels
    int b = idx / DHW;
    int s = idx - b * DHW;
    int w = s % WW;
    int t = s / WW;
    int h = t % HH;
    int d = t / HH;

    const float* fl = flow + (size_t)b * 3 * DHW;
    float4 fd4 = *reinterpret_cast<const float4*>(fl + s);
    float4 fh4 = *reinterpret_cast<const float4*>(fl + DHW + s);
    float4 fw4 = *reinterpret_cast<const float4*>(fl + 2 * DHW + s);

    const float* sv = src + (size_t)b * DHW;

    float cd_base = (float)d;
    float ch_base = (float)h;
    float cw_base = (float)w;

    float4 res;
    res.x = sample_one(sv, cd_base + fd4.x, ch_base + fh4.x, cw_base + 0.0f + fw4.x);
    res.y = sample_one(sv, cd_base + fd4.y, ch_base + fh4.y, cw_base + 1.0f + fw4.y);
    res.z = sample_one(sv, cd_base + fd4.z, ch_base + fh4.z, cw_base + 2.0f + fw4.z);
    res.w = sample_one(sv, cd_base + fd4.w, ch_base + fh4.w, cw_base + 3.0f + fw4.w);

    *reinterpret_cast<float4*>(out + idx) = res;
}

extern "C" void kernel_launch(void* const* d_in, const int* in_sizes, int n_in,
                              void* d_out, int out_size) {
    const float* src  = (const float*)d_in[0];
    const float* flow = (const float*)d_in[1];
    float* out = (float*)d_out;

    const int nvec = (BB * DHW) / 4;
    const int threads = 256;
    const int blocks = (nvec + threads - 1) / threads;
    spatial_transformer_kernel<<<blocks, threads>>>(src, flow, out);
}

// round 3
// speedup vs baseline: 1.6062x; 1.5005x over previous
#include <cuda_runtime.h>
#include <cuda_fp16.h>

// SpatialTransformer: trilinear grid-sample, border padding, align_corners=True.
// src  [B=2, C=1, D=160, H=192, W=224] fp32
// flow [B=2, 3, D, H, W] fp32
// out  [B=2, C=1, D, H, W] fp32
//
// R3: two-phase, L1-request-minimized.
//  Phase 1 (repack): build Q[b][d][h][w] = 2x2x2 corner cube as 8 fp16 = 16B,
//           border-clamped exactly like the reference (min(+1, dim-1)).
//  Phase 2 (gather): ONE scattered LDG.128 per output voxel fetches all 8
//           corners; trilinear weights stay fp32-exact.
// Prior kernels were L1 tag-request bound at ~44us per scattered req/voxel;
// this cuts 5 req/voxel -> 1.

#define DD 160
#define HH 192
#define WW 224
#define BB 2
#define HW (HH * WW)
#define DHW (DD * HH * WW)

// 220 MB scratch: 8 halves per voxel, 16B-aligned.
__device__ __align__(16) static __half Qbuf[(size_t)BB * DHW * 8];

// ---------------- Phase 1: corner repack ----------------
__global__ __launch_bounds__(256) void repack_kernel(const float* __restrict__ src) {
    int idx = blockIdx.x * blockDim.x + threadIdx.x;
    if (idx >= BB * DHW) return;

    int b = idx / DHW;
    int s = idx - b * DHW;
    int w = s % WW;
    int t = s / WW;
    int h = t % HH;
    int d = t / HH;

    const float* __restrict__ sv = src + (size_t)b * DHW;

    int w1 = min(w + 1, WW - 1);
    int h1 = min(h + 1, HH - 1);
    int d1 = min(d + 1, DD - 1);

    int r00 = d * HW + h * WW;
    int r01 = d * HW + h1 * WW;
    int r10 = d1 * HW + h * WW;
    int r11 = d1 * HW + h1 * WW;

    float c000 = __ldg(sv + r00 + w);
    float c001 = __ldg(sv + r00 + w1);
    float c010 = __ldg(sv + r01 + w);
    float c011 = __ldg(sv + r01 + w1);
    float c100 = __ldg(sv + r10 + w);
    float c101 = __ldg(sv + r10 + w1);
    float c110 = __ldg(sv + r11 + w);
    float c111 = __ldg(sv + r11 + w1);

    __half2 p0 = __floats2half2_rn(c000, c001);
    __half2 p1 = __floats2half2_rn(c010, c011);
    __half2 p2 = __floats2half2_rn(c100, c101);
    __half2 p3 = __floats2half2_rn(c110, c111);

    uint4 packed;
    packed.x = *reinterpret_cast<unsigned int*>(&p0);
    packed.y = *reinterpret_cast<unsigned int*>(&p1);
    packed.z = *reinterpret_cast<unsigned int*>(&p2);
    packed.w = *reinterpret_cast<unsigned int*>(&p3);

    reinterpret_cast<uint4*>(Qbuf)[idx] = packed;   // lane-contiguous 16B store
}

// ---------------- Phase 2: gather ----------------
__device__ __forceinline__ float sample_packed(const uint4* __restrict__ Q4,
                                               float cd, float ch, float cw) {
    cd = fminf(fmaxf(cd, 0.0f), (float)(DD - 1));
    ch = fminf(fmaxf(ch, 0.0f), (float)(HH - 1));
    cw = fminf(fmaxf(cw, 0.0f), (float)(WW - 1));

    int d0 = (int)cd;   // coords >= 0, trunc == floor
    int h0 = (int)ch;
    int w0 = (int)cw;

    float fd = cd - (float)d0;
    float fh = ch - (float)h0;
    float fw = cw - (float)w0;

    uint4 q = __ldg(Q4 + (d0 * HW + h0 * WW + w0));   // all 8 corners, 16B

    float2 a = __half22float2(*reinterpret_cast<__half2*>(&q.x));  // c000,c001
    float2 bb = __half22float2(*reinterpret_cast<__half2*>(&q.y)); // c010,c011
    float2 c = __half22float2(*reinterpret_cast<__half2*>(&q.z));  // c100,c101
    float2 e = __half22float2(*reinterpret_cast<__half2*>(&q.w));  // c110,c111

    float c00 = fmaf(fw, a.y - a.x, a.x);
    float c01 = fmaf(fw, bb.y - bb.x, bb.x);
    float c10 = fmaf(fw, c.y - c.x, c.x);
    float c11 = fmaf(fw, e.y - e.x, e.x);
    float c0  = fmaf(fh, c01 - c00, c00);
    float c1  = fmaf(fh, c11 - c10, c10);
    return fmaf(fd, c1 - c0, c0);
}

__global__ __launch_bounds__(256) void gather_kernel(
    const float* __restrict__ flow,
    float* __restrict__ out) {
    int tid = blockIdx.x * blockDim.x + threadIdx.x;
    const int nvec = (BB * DHW) / 4;
    if (tid >= nvec) return;

    int idx = tid * 4;              // first of 4 consecutive-W voxels
    int b = idx / DHW;
    int s = idx - b * DHW;
    int w = s % WW;
    int t = s / WW;
    int h = t % HH;
    int d = t / HH;

    const float* fl = flow + (size_t)b * 3 * DHW;
    float4 fd4 = *reinterpret_cast<const float4*>(fl + s);
    float4 fh4 = *reinterpret_cast<const float4*>(fl + DHW + s);
    float4 fw4 = *reinterpret_cast<const float4*>(fl + 2 * DHW + s);

    const uint4* Q4 = reinterpret_cast<const uint4*>(Qbuf) + (size_t)b * DHW;

    float cd_base = (float)d;
    float ch_base = (float)h;
    float cw_base = (float)w;

    float4 res;
    res.x = sample_packed(Q4, cd_base + fd4.x, ch_base + fh4.x, cw_base + 0.0f + fw4.x);
    res.y = sample_packed(Q4, cd_base + fd4.y, ch_base + fh4.y, cw_base + 1.0f + fw4.y);
    res.z = sample_packed(Q4, cd_base + fd4.z, ch_base + fh4.z, cw_base + 2.0f + fw4.z);
    res.w = sample_packed(Q4, cd_base + fd4.w, ch_base + fh4.w, cw_base + 3.0f + fw4.w);

    *reinterpret_cast<float4*>(out + idx) = res;
}

extern "C" void kernel_launch(void* const* d_in, const int* in_sizes, int n_in,
                              void* d_out, int out_size) {
    const float* src  = (const float*)d_in[0];
    const float* flow = (const float*)d_in[1];
    float* out = (float*)d_out;

    {
        const int n = BB * DHW;
        const int threads = 256;
        repack_kernel<<<(n + threads - 1) / threads, threads>>>(src);
    }
    {
        const int nvec = (BB * DHW) / 4;
        const int threads = 256;
        gather_kernel<<<(nvec + threads - 1) / threads, threads>>>(flow, out);
    }
}